// round 10
// baseline (speedup 1.0000x reference)
#include <cuda_runtime.h>
#include <cstdint>

typedef unsigned long long ull_t;

// ---- packed f32x2 helpers ----
__device__ __forceinline__ void ffma2(ull_t &acc, ull_t a, ull_t b) {
    asm volatile("fma.rn.f32x2 %0, %1, %2, %0;" : "+l"(acc) : "l"(a), "l"(b));
}
__device__ __forceinline__ ull_t add2(ull_t a, ull_t b) {
    ull_t r; asm("add.rn.f32x2 %0, %1, %2;" : "=l"(r) : "l"(a), "l"(b)); return r;
}
__device__ __forceinline__ float hsum2(ull_t v) {
    float lo, hi; asm("mov.b64 {%0,%1}, %2;" : "=f"(lo), "=f"(hi) : "l"(v));
    return lo + hi;
}
__device__ __forceinline__ ull_t pack2(float lo, float hi) {
    ull_t r; asm("mov.b64 %0, {%1, %2};" : "=l"(r) : "f"(lo), "f"(hi)); return r;
}
__device__ __forceinline__ ull_t mul2(ull_t a, ull_t b) {
    ull_t r; asm("mul.rn.f32x2 %0, %1, %2;" : "=l"(r) : "l"(a), "l"(b)); return r;
}

__device__ __forceinline__ void cp_async16(uint32_t dst, const void* src, int src_sz) {
    asm volatile("cp.async.cg.shared.global [%0], [%1], 16, %2;"
                 :: "r"(dst), "l"(src), "r"(src_sz));
}
__device__ __forceinline__ void cp_commit() {
    asm volatile("cp.async.commit_group;");
}
__device__ __forceinline__ void cp_wait1() {
    asm volatile("cp.async.wait_group 1;" ::: "memory");
}
__device__ __forceinline__ void named_bar(int id, int cnt) {
    asm volatile("bar.sync %0, %1;" :: "r"(id), "r"(cnt) : "memory");
}

// =====================================================================
// Warp-specialized + batch-interleaved kernel. Block = 128 thr, 2 batches:
//   warps 0-1 (tid 0-63):   recurrence for BOTH batches, interleaved in one
//                           instruction stream (thread = channel j; each
//                           combined iter does step t of batch0 AND batch1,
//                           then ONE 64-thr barrier -> bar cost/step halved,
//                           chains mutually hide latency).
//   warps 2-3 (tid 64-127): xp producers for both batches, one chunk ahead
//                           (cp.async raw x -> dot with alpha*W_in -> xpbuf).
// Barriers: 1 = rec step bar (64 thr); 2 = producer visibility (64 thr);
//           3 = chunk rendezvous (128 thr).
// =====================================================================
__global__ void __launch_bounds__(128, 1)
ctrnn_ws2_kernel(const float* __restrict__ x,
                 const float* __restrict__ W_in,
                 const float* __restrict__ b_in,
                 const float* __restrict__ W_hh,
                 const float* __restrict__ b_hh,
                 float* __restrict__ out,
                 int B, int T)
{
    constexpr int H  = 64;
    constexpr int D  = 32;
    constexpr int CH = 32;   // timesteps per chunk

    const int tid  = threadIdx.x;
    const int role = tid >> 6;       // 0 = recurrence, 1 = xp producer
    const int j    = tid & 63;       // channel
    const int b0   = blockIdx.x * 2;
    const int b1   = b0 + 1;
    const bool act0 = (b0 < B);
    const bool act1 = (b1 < B);
    const int bc0  = act0 ? b0 : (B - 1);
    const int bc1  = act1 ? b1 : (B - 1);

    __shared__ __align__(16) float hbuf[2][2][H];          // [ping][batch][H]
    __shared__ __align__(16) float xbuf[2][2][CH * D];     // raw x ring
    __shared__ __align__(16) float xpbuf[2][2][CH][H];     // xp ring

    const float alpha = (float)(16.67 / 40.0);
    const float oma   = (float)(1.0 - 16.67 / 40.0);
    const ull_t alpha2 = pack2(alpha, alpha);

    const int nchunk = (T + CH - 1) / CH;

    if (role == 1) {
        // ======================= XP PRODUCER =======================
        ull_t iu[16];
        {
            const ulonglong2* wr = reinterpret_cast<const ulonglong2*>(W_in + j * D);
#pragma unroll
            for (int m = 0; m < 8; m++) {
                ulonglong2 v = wr[m];
                iu[2 * m]     = mul2(v.x, alpha2);
                iu[2 * m + 1] = mul2(v.y, alpha2);
            }
        }
        const float ab = alpha * (b_in[j] + b_hh[j]);

        const int bcs[2] = { bc0, bc1 };
        const bool acts[2] = { act0, act1 };

        // stage raw x chunk c for BOTH batches; one commit group
        auto issue_chunk = [&](int c, int buf) {
#pragma unroll
            for (int sbb = 0; sbb < 2; sbb++) {
                const float* src = x + ((size_t)bcs[sbb] * T + (size_t)c * CH) * D;
                const char* srcb = (const char*)src;
                uint32_t dstb = (uint32_t)__cvta_generic_to_shared(&xbuf[buf][sbb][0]);
#pragma unroll
                for (int q = 0; q < 4; q++) {
                    int off16 = j + 64 * q;          // 256 units per batch-chunk
                    int row   = off16 >> 3;          // 8 x 16B per timestep row
                    bool ok   = acts[sbb] && (c * CH + row) < T;
                    const void* s = ok ? (const void*)(srcb + (size_t)off16 * 16)
                                       : (const void*)x;
                    cp_async16(dstb + off16 * 16, s, ok ? 16 : 0);
                }
            }
            cp_commit();
        };

        // xp for chunk c, both batches
        auto produce = [&](int c) {
            const int rb   = c & 1;
            const int tend = min(CH, T - c * CH);
            for (int r = 0; r < tend; r++) {
#pragma unroll
                for (int sbb = 0; sbb < 2; sbb++) {
                    const ulonglong2* xr =
                        reinterpret_cast<const ulonglong2*>(&xbuf[rb][sbb][r * D]);
                    ull_t c0 = 0ull, c1 = 0ull, c2 = 0ull, c3 = 0ull;
#pragma unroll
                    for (int m = 0; m < 8; m++) {
                        ulonglong2 v = xr[m];
                        ffma2((m & 1) ? c1 : c0, iu[2 * m],     v.x);
                        ffma2((m & 1) ? c3 : c2, iu[2 * m + 1], v.y);
                    }
                    xpbuf[rb][sbb][r][j] =
                        hsum2(add2(add2(c0, c1), add2(c2, c3))) + ab;
                }
            }
        };

        issue_chunk(0, 0);
        if (nchunk > 1) issue_chunk(1, 1); else cp_commit();
        cp_wait1();                 // chunk 0 landed
        named_bar(2, 64);           // producer-group visibility
        produce(0);
        named_bar(3, 128);          // xp chunk 0 ready

        for (int c = 0; c < nchunk; c++) {
            if (c + 2 < nchunk) issue_chunk(c + 2, c & 1); else cp_commit();
            if (c + 1 < nchunk) {
                cp_wait1();
                named_bar(2, 64);
                produce(c + 1);
            }
            named_bar(3, 128);      // end-of-chunk rendezvous
        }
    } else {
        // ======================= RECURRENCE (both batches) =======================
        ull_t wu[32];
        {
            const ulonglong2* wr = reinterpret_cast<const ulonglong2*>(W_hh + j * H);
#pragma unroll
            for (int m = 0; m < 16; m++) {
                ulonglong2 v = wr[m];
                wu[2 * m]     = mul2(v.x, alpha2);
                wu[2 * m + 1] = mul2(v.y, alpha2);
            }
        }

        hbuf[0][0][j] = 0.0f;
        hbuf[0][1][j] = 0.0f;
        float hj0 = 0.0f, hj1 = 0.0f;

        int cur = 0;
        const size_t out0 = (size_t)bc0 * T * H + j;
        const size_t out1 = (size_t)bc1 * T * H + j;

        named_bar(3, 128);          // wait for xp chunk 0 (also covers hbuf init)

        for (int c = 0; c < nchunk; c++) {
            const int xb   = c & 1;
            const int tend = min(CH, T - c * CH);
            const size_t o0c = out0 + (size_t)c * CH * H;
            const size_t o1c = out1 + (size_t)c * CH * H;

#define STEP2(tt)                                                                   \
    {                                                                               \
        const ulonglong2* hp0 = reinterpret_cast<const ulonglong2*>(hbuf[cur][0]); \
        const ulonglong2* hp1 = reinterpret_cast<const ulonglong2*>(hbuf[cur][1]); \
        ull_t a0 = pack2(xpbuf[xb][0][(tt)][j], 0.0f);                              \
        ull_t a1 = 0ull, a2 = 0ull, a3 = 0ull;                                      \
        ull_t d0 = pack2(xpbuf[xb][1][(tt)][j], 0.0f);                              \
        ull_t d1 = 0ull, d2 = 0ull, d3 = 0ull;                                      \
        _Pragma("unroll")                                                           \
        for (int m = 0; m < 16; m++) {                                              \
            ulonglong2 hv0 = hp0[m];                                                \
            ulonglong2 hv1 = hp1[m];                                                \
            ffma2((m & 1) ? a1 : a0, wu[2 * m],     hv0.x);                         \
            ffma2((m & 1) ? a3 : a2, wu[2 * m + 1], hv0.y);                         \
            ffma2((m & 1) ? d1 : d0, wu[2 * m],     hv1.x);                         \
            ffma2((m & 1) ? d3 : d2, wu[2 * m + 1], hv1.y);                         \
        }                                                                           \
        float p0 = hsum2(add2(add2(a0, a1), add2(a2, a3)));                         \
        float p1 = hsum2(add2(add2(d0, d1), add2(d2, d3)));                         \
        float h0n = fmaxf(fmaf(hj0, oma, p0), 0.0f);                                \
        float h1n = fmaxf(fmaf(hj1, oma, p1), 0.0f);                                \
        hbuf[cur ^ 1][0][j] = h0n;                                                  \
        hbuf[cur ^ 1][1][j] = h1n;                                                  \
        if (act0) out[o0c + (size_t)(tt) * H] = h0n;                                \
        if (act1) out[o1c + (size_t)(tt) * H] = h1n;                                \
        hj0 = h0n; hj1 = h1n;                                                       \
        cur ^= 1;                                                                   \
        named_bar(1, 64);                                                           \
    }

            if (tend == CH) {
#pragma unroll 2
                for (int tt = 0; tt < CH; tt++) STEP2(tt)
            } else {
                for (int tt = 0; tt < tend; tt++) STEP2(tt)
            }
#undef STEP2

            named_bar(3, 128);      // chunk rendezvous with producers
        }

        // h_last appended after outputs
        if (act0) out[(size_t)B * T * H + (size_t)b0 * H + j] = hj0;
        if (act1) out[(size_t)B * T * H + (size_t)b1 * H + j] = hj1;
    }
}

extern "C" void kernel_launch(void* const* d_in, const int* in_sizes, int n_in,
                              void* d_out, int out_size)
{
    const float* x    = (const float*)d_in[0];
    // d_in[1] = seq_lengths: forward-dead (mask only gates gradients)
    const float* W_in = (const float*)d_in[2];
    const float* b_in = (const float*)d_in[3];
    const float* W_hh = (const float*)d_in[4];
    const float* b_hh = (const float*)d_in[5];
    float* out = (float*)d_out;

    const int B = in_sizes[1];
    const int H = in_sizes[5];
    const int D = in_sizes[2] / H;
    const long long T = (long long)in_sizes[0] / ((long long)B * D);

    const int grid = (B + 1) / 2;
    ctrnn_ws2_kernel<<<grid, 128>>>(x, W_in, b_in, W_hh, b_hh, out, B, (int)T);
}

// round 11
// speedup vs baseline: 1.2331x; 1.2331x over previous
#include <cuda_runtime.h>
#include <cstdint>

typedef unsigned long long ull_t;

// ---- packed f32x2 helpers ----
__device__ __forceinline__ void ffma2(ull_t &acc, ull_t a, ull_t b) {
    asm volatile("fma.rn.f32x2 %0, %1, %2, %0;" : "+l"(acc) : "l"(a), "l"(b));
}
__device__ __forceinline__ ull_t add2(ull_t a, ull_t b) {
    ull_t r; asm("add.rn.f32x2 %0, %1, %2;" : "=l"(r) : "l"(a), "l"(b)); return r;
}
__device__ __forceinline__ float hsum2(ull_t v) {
    float lo, hi; asm("mov.b64 {%0,%1}, %2;" : "=f"(lo), "=f"(hi) : "l"(v));
    return lo + hi;
}
__device__ __forceinline__ ull_t pack2(float lo, float hi) {
    ull_t r; asm("mov.b64 %0, {%1, %2};" : "=l"(r) : "f"(lo), "f"(hi)); return r;
}
__device__ __forceinline__ ull_t mul2(ull_t a, ull_t b) {
    ull_t r; asm("mul.rn.f32x2 %0, %1, %2;" : "=l"(r) : "l"(a), "l"(b)); return r;
}

__device__ __forceinline__ void cp_async16(uint32_t dst, const void* src, int src_sz) {
    asm volatile("cp.async.cg.shared.global [%0], [%1], 16, %2;"
                 :: "r"(dst), "l"(src), "r"(src_sz));
}
__device__ __forceinline__ void cp_commit() {
    asm volatile("cp.async.commit_group;");
}
__device__ __forceinline__ void cp_wait1() {
    asm volatile("cp.async.wait_group 1;" ::: "memory");
}
__device__ __forceinline__ void named_bar(int id, int cnt) {
    asm volatile("bar.sync %0, %1;" :: "r"(id), "r"(cnt) : "memory");
}

// =====================================================================
// Warp-specialized fused kernel, ARBITER-AWARE role placement.
// Intra-SMSP arbitration is highest-wid-first, so the latency-critical
// recurrence warps get the HIGH warp ids and producers the low ones:
//   warps 0-1: xp producer batch0   (SMSP 0,1)   [low priority]
//   warps 2-3: xp producer batch1   (SMSP 2,3)
//   warps 4-5: recurrence batch0    (SMSP 0,1)   [high priority]
//   warps 6-7: recurrence batch1    (SMSP 2,3)
// Producers stage raw x (cp.async) and compute xp = alpha*(x·W_in^T + b)
// one chunk ahead into a 2-deep smem ring; rec warps run the serial scan.
// Barriers: 1+sb = rec step bar (64 thr); 5+sb = producer visibility (64);
//           3+sb = chunk rendezvous (128 thr, rec+prod of batch sb).
// =====================================================================
__global__ void __launch_bounds__(256, 1)
ctrnn_ws3_kernel(const float* __restrict__ x,
                 const float* __restrict__ W_in,
                 const float* __restrict__ b_in,
                 const float* __restrict__ W_hh,
                 const float* __restrict__ b_hh,
                 float* __restrict__ out,
                 int B, int T)
{
    constexpr int H  = 64;
    constexpr int D  = 32;
    constexpr int CH = 32;   // timesteps per chunk

    const int tid  = threadIdx.x;
    const int rec  = tid >> 7;         // 0 = xp producer (wid 0-3), 1 = recurrence (wid 4-7)
    const int sb   = (tid >> 6) & 1;   // batch slot
    const int j    = tid & 63;         // channel
    const int b    = blockIdx.x * 2 + sb;
    const bool active = (b < B);
    const int bc   = active ? b : (B - 1);

    __shared__ __align__(16) float hbuf[2][2][H];          // 1KB
    __shared__ __align__(16) float xbuf[2][2][CH * D];     // raw x ring, 16KB
    __shared__ __align__(16) float xpbuf[2][2][CH][H];     // xp ring, 32KB

    const float alpha = (float)(16.67 / 40.0);
    const float oma   = (float)(1.0 - 16.67 / 40.0);
    const ull_t alpha2 = pack2(alpha, alpha);

    const int nchunk = (T + CH - 1) / CH;

    if (rec == 0) {
        // ================= XP PRODUCER (low-priority warps) =================
        ull_t iu[16];
        {
            const ulonglong2* wr = reinterpret_cast<const ulonglong2*>(W_in + j * D);
#pragma unroll
            for (int m = 0; m < 8; m++) {
                ulonglong2 v = wr[m];
                iu[2 * m]     = mul2(v.x, alpha2);
                iu[2 * m + 1] = mul2(v.y, alpha2);
            }
        }
        const float ab = alpha * (b_in[j] + b_hh[j]);

        // stage raw x chunk c into xbuf[buf]: 4KB = 256 x 16B; 64 thr -> 4 each
        auto issue_chunk = [&](int c, int buf) {
            const float* src = x + ((size_t)bc * T + (size_t)c * CH) * D;
            const char* srcb = (const char*)src;
            uint32_t dstb = (uint32_t)__cvta_generic_to_shared(&xbuf[buf][sb][0]);
#pragma unroll
            for (int q = 0; q < 4; q++) {
                int off16 = j + 64 * q;
                int row   = off16 >> 3;          // 8 units (128B) per row
                bool ok   = active && (c * CH + row) < T;
                const void* s = ok ? (const void*)(srcb + (size_t)off16 * 16)
                                   : (const void*)x;
                cp_async16(dstb + off16 * 16, s, ok ? 16 : 0);
            }
            cp_commit();
        };

        // xp of chunk c (x in xbuf[c&1]) -> xpbuf[c&1]; thread owns channel j
        auto produce = [&](int c) {
            const int rb   = c & 1;
            const int tend = min(CH, T - c * CH);
            for (int r = 0; r < tend; r++) {
                const ulonglong2* xr =
                    reinterpret_cast<const ulonglong2*>(&xbuf[rb][sb][r * D]);
                ull_t c0 = 0ull, c1 = 0ull, c2 = 0ull, c3 = 0ull;
#pragma unroll
                for (int m = 0; m < 8; m++) {
                    ulonglong2 v = xr[m];
                    ffma2((m & 1) ? c1 : c0, iu[2 * m],     v.x);
                    ffma2((m & 1) ? c3 : c2, iu[2 * m + 1], v.y);
                }
                xpbuf[rb][sb][r][j] =
                    hsum2(add2(add2(c0, c1), add2(c2, c3))) + ab;
            }
        };

        // prologue: stage ch0, ch1; produce xp0
        issue_chunk(0, 0);
        if (nchunk > 1) issue_chunk(1, 1); else cp_commit();
        cp_wait1();                 // own ch0 copies done
        named_bar(5 + sb, 64);      // producer-group ch0 visible
        produce(0);
        named_bar(3 + sb, 128);     // rendezvous: xp0 ready for rec warps

        for (int c = 0; c < nchunk; c++) {
            if (c + 2 < nchunk) issue_chunk(c + 2, c & 1); else cp_commit();
            if (c + 1 < nchunk) {
                cp_wait1();             // ch(c+1) landed
                named_bar(5 + sb, 64);  // group visibility of ch(c+1)
                produce(c + 1);         // fills rec's idle issue slots
            }
            named_bar(3 + sb, 128);     // end-of-chunk rendezvous with rec
        }
    } else {
        // ================= RECURRENCE (high-priority warps) =================
        ull_t wu[32];
        {
            const ulonglong2* wr = reinterpret_cast<const ulonglong2*>(W_hh + j * H);
#pragma unroll
            for (int m = 0; m < 16; m++) {
                ulonglong2 v = wr[m];
                wu[2 * m]     = mul2(v.x, alpha2);
                wu[2 * m + 1] = mul2(v.y, alpha2);
            }
        }

        hbuf[0][sb][j] = 0.0f;
        float hj = 0.0f;

        int cur = 0;
        const size_t outbase = (size_t)bc * T * H + j;

        named_bar(3 + sb, 128);     // wait for xp chunk 0 (covers hbuf init too)

        for (int c = 0; c < nchunk; c++) {
            const int xb   = c & 1;
            const int tend = min(CH, T - c * CH);
            const size_t obase_c = outbase + (size_t)c * CH * H;

            // leak (oma*hj) + xps folded into accumulator init: off the tail chain
#define STEP_BODY(tt)                                                              \
    {                                                                              \
        const ulonglong2* hp = reinterpret_cast<const ulonglong2*>(hbuf[cur][sb]); \
        const float xps = xpbuf[xb][sb][(tt)][j];                                  \
        ull_t a0 = pack2(fmaf(hj, oma, xps), 0.0f);                                \
        ull_t a1 = 0ull, a2 = 0ull, a3 = 0ull;                                     \
        _Pragma("unroll")                                                          \
        for (int m = 0; m < 16; m++) {                                             \
            ulonglong2 hv = hp[m];                                                 \
            ffma2((m & 1) ? a1 : a0, wu[2 * m],     hv.x);                         \
            ffma2((m & 1) ? a3 : a2, wu[2 * m + 1], hv.y);                         \
        }                                                                          \
        float p = hsum2(add2(add2(a0, a1), add2(a2, a3)));                         \
        float hnew = fmaxf(p, 0.0f);                                               \
        hbuf[cur ^ 1][sb][j] = hnew;                                               \
        if (active) out[obase_c + (size_t)(tt) * H] = hnew;                        \
        hj = hnew;                                                                 \
        cur ^= 1;                                                                  \
        named_bar(1 + sb, 64);                                                     \
    }

            if (tend == CH) {
#pragma unroll 4
                for (int tt = 0; tt < CH; tt++) STEP_BODY(tt)
            } else {
                for (int tt = 0; tt < tend; tt++) STEP_BODY(tt)
            }
#undef STEP_BODY

            named_bar(3 + sb, 128);   // chunk done; next xp ring slot ready
        }

        // h_last appended after outputs
        if (active) out[(size_t)B * T * H + (size_t)b * H + j] = hj;
    }
}

extern "C" void kernel_launch(void* const* d_in, const int* in_sizes, int n_in,
                              void* d_out, int out_size)
{
    const float* x    = (const float*)d_in[0];
    // d_in[1] = seq_lengths: forward-dead (mask only gates gradients)
    const float* W_in = (const float*)d_in[2];
    const float* b_in = (const float*)d_in[3];
    const float* W_hh = (const float*)d_in[4];
    const float* b_hh = (const float*)d_in[5];
    float* out = (float*)d_out;

    const int B = in_sizes[1];
    const int H = in_sizes[5];
    const int D = in_sizes[2] / H;
    const long long T = (long long)in_sizes[0] / ((long long)B * D);

    const int grid = (B + 1) / 2;
    ctrnn_ws3_kernel<<<grid, 256>>>(x, W_in, b_in, W_hh, b_hh, out, B, (int)T);
}

// round 12
// speedup vs baseline: 1.2962x; 1.0512x over previous
#include <cuda_runtime.h>
#include <cstdint>

typedef unsigned long long ull_t;

// ---- packed f32x2 helpers ----
__device__ __forceinline__ void ffma2(ull_t &acc, ull_t a, ull_t b) {
    asm volatile("fma.rn.f32x2 %0, %1, %2, %0;" : "+l"(acc) : "l"(a), "l"(b));
}
__device__ __forceinline__ ull_t add2(ull_t a, ull_t b) {
    ull_t r; asm("add.rn.f32x2 %0, %1, %2;" : "=l"(r) : "l"(a), "l"(b)); return r;
}
__device__ __forceinline__ float hsum2(ull_t v) {
    float lo, hi; asm("mov.b64 {%0,%1}, %2;" : "=f"(lo), "=f"(hi) : "l"(v));
    return lo + hi;
}
__device__ __forceinline__ void unpack2(float &lo, float &hi, ull_t v) {
    asm("mov.b64 {%0,%1}, %2;" : "=f"(lo), "=f"(hi) : "l"(v));
}
__device__ __forceinline__ ull_t pack2(float lo, float hi) {
    ull_t r; asm("mov.b64 %0, {%1, %2};" : "=l"(r) : "f"(lo), "f"(hi)); return r;
}
__device__ __forceinline__ ull_t mul2(ull_t a, ull_t b) {
    ull_t r; asm("mul.rn.f32x2 %0, %1, %2;" : "=l"(r) : "l"(a), "l"(b)); return r;
}

__device__ __forceinline__ void cp_async16(uint32_t dst, const void* src, int src_sz) {
    asm volatile("cp.async.cg.shared.global [%0], [%1], 16, %2;"
                 :: "r"(dst), "l"(src), "r"(src_sz));
}
__device__ __forceinline__ void cp_commit() {
    asm volatile("cp.async.commit_group;");
}
__device__ __forceinline__ void cp_wait1() {
    asm volatile("cp.async.wait_group 1;" ::: "memory");
}
__device__ __forceinline__ void named_bar(int id, int cnt) {
    asm volatile("bar.sync %0, %1;" :: "r"(id), "r"(cnt) : "memory");
}

// Dynamic smem layout (81920 B total):
//   hist : ull  [2][64][32]  h history ring (2 chunks deep), (h2q,h2q+1) pairs
//   xpb  : ull  [2][2][32][32] xp ring [ringbuf][batch][row][pair]
//   xb   : f32  [2][2][32*32]  raw x ring
#define SMEM_HIST 0
#define SMEM_XP   32768
#define SMEM_XB   65536
#define SMEM_TOTAL 81920

// =====================================================================
// Warp-synchronous warp-specialized kernel. Block = 128 thr, 2 batches:
//   w0: recurrence batch0 (SMSP0)   w1: recurrence batch1 (SMSP1)
//   w2: producer  batch0 (SMSP2)   w3: producer  batch1 (SMSP3)
// Rec warp: thread q owns channels (2q, 2q+1); both dots share the same
// 16 broadcast LDS.128 h-loads; h exchange = one STS.64 + __syncwarp()
// (NO cross-warp barrier in the step loop). Producers stage x (cp.async),
// compute xp one chunk ahead, AND flush the h-history ring to gmem one
// chunk behind (rec does no STG). Chunk rendezvous: named bar (1+sb, 64).
// =====================================================================
__global__ void __launch_bounds__(128, 1)
ctrnn_ws4_kernel(const float* __restrict__ x,
                 const float* __restrict__ W_in,
                 const float* __restrict__ b_in,
                 const float* __restrict__ W_hh,
                 const float* __restrict__ b_hh,
                 float* __restrict__ out,
                 int B, int T)
{
    constexpr int H  = 64;
    constexpr int D  = 32;
    constexpr int CH = 32;

    extern __shared__ char smem[];
    ull_t* hist = (ull_t*)(smem + SMEM_HIST);   // [sb*2048 + slot*32 + q]
    ull_t* xpb  = (ull_t*)(smem + SMEM_XP);     // [rb*2048 + sb*1024 + r*32 + q]
    float* xb   = (float*)(smem + SMEM_XB);     // [rb*2048 + sb*1024 + r*D + d]

    const int tid  = threadIdx.x;
    const int wid  = tid >> 5;
    const int q    = tid & 31;        // channel-pair index
    const int sb   = wid & 1;         // batch slot
    const int role = wid >> 1;        // 0 = recurrence, 1 = producer
    const int b    = blockIdx.x * 2 + sb;
    const bool active = (b < B);
    const int bc   = active ? b : (B - 1);

    const float alpha = (float)(16.67 / 40.0);
    const float oma   = (float)(1.0 - 16.67 / 40.0);
    const ull_t alpha2 = pack2(alpha, alpha);

    const int nchunk = (T + CH - 1) / CH;

    if (role == 1) {
        // ===================== PRODUCER / FLUSHER (own SMSP) =====================
        // alpha-scaled W_in rows 2q, 2q+1 as (k,k+1) pairs
        ull_t iA[16], iB[16];
        {
            const ulonglong2* ra = reinterpret_cast<const ulonglong2*>(W_in + (2 * q) * D);
            const ulonglong2* rb = reinterpret_cast<const ulonglong2*>(W_in + (2 * q + 1) * D);
#pragma unroll
            for (int m = 0; m < 8; m++) {
                ulonglong2 va = ra[m], vb = rb[m];
                iA[2 * m] = mul2(va.x, alpha2); iA[2 * m + 1] = mul2(va.y, alpha2);
                iB[2 * m] = mul2(vb.x, alpha2); iB[2 * m + 1] = mul2(vb.y, alpha2);
            }
        }
        const float abA = alpha * (b_in[2 * q]     + b_hh[2 * q]);
        const float abB = alpha * (b_in[2 * q + 1] + b_hh[2 * q + 1]);

        auto issue_chunk = [&](int c, int buf) {
            const float* src = x + ((size_t)bc * T + (size_t)c * CH) * D;
            uint32_t dstb = (uint32_t)__cvta_generic_to_shared(&xb[buf * 2048 + sb * 1024]);
#pragma unroll
            for (int i = 0; i < 8; i++) {
                int off16 = q + 32 * i;          // 256 x 16B units per chunk
                int row   = off16 >> 3;          // 8 units per timestep row
                bool ok   = active && (c * CH + row) < T;
                const void* s = ok ? (const void*)((const char*)src + (size_t)off16 * 16)
                                   : (const void*)x;
                cp_async16(dstb + off16 * 16, s, ok ? 16 : 0);
            }
            cp_commit();
        };

        auto produce = [&](int c) {
            const int rb   = c & 1;
            const int tend = min(CH, T - c * CH);
            const float* xrow0 = &xb[rb * 2048 + sb * 1024];
            ull_t* dst = &xpb[rb * 2048 + sb * 1024];
            for (int r = 0; r < tend; r++) {
                const ulonglong2* xr =
                    reinterpret_cast<const ulonglong2*>(xrow0 + r * D);
                ull_t aA0 = 0ull, aA1 = 0ull, aB0 = 0ull, aB1 = 0ull;
#pragma unroll
                for (int m = 0; m < 8; m++) {
                    ulonglong2 v = xr[m];
                    ffma2(aA0, iA[2 * m],     v.x);
                    ffma2(aA1, iA[2 * m + 1], v.y);
                    ffma2(aB0, iB[2 * m],     v.x);
                    ffma2(aB1, iB[2 * m + 1], v.y);
                }
                float pA = hsum2(add2(aA0, aA1)) + abA;
                float pB = hsum2(add2(aB0, aB1)) + abB;
                dst[r * 32 + q] = pack2(pA, pB);
            }
        };

        auto flushc = [&](int c) {
            if (!active) return;
            const int tend = min(CH, T - c * CH);
            for (int r = 0; r < tend; r++) {
                int t = c * CH + r;
                ull_t v = hist[sb * 2048 + (t & 63) * 32 + q];
                *(ull_t*)(out + ((size_t)bc * T + t) * H + 2 * q) = v;  // 2 floats
            }
        };

        issue_chunk(0, 0);
        if (nchunk > 1) issue_chunk(1, 1); else cp_commit();
        cp_wait1();            // chunk 0 landed
        __syncwarp();          // intra-warp visibility
        produce(0);
        named_bar(1 + sb, 64); // xp chunk 0 ready

        for (int c = 0; c < nchunk; c++) {
            if (c + 2 < nchunk) issue_chunk(c + 2, c & 1); else cp_commit();
            if (c + 1 < nchunk) {
                cp_wait1();        // chunk c+1 landed
                __syncwarp();
                produce(c + 1);    // xp into ring slot (c+1)&1
            }
            if (c > 0) flushc(c - 1);   // flush finished chunk (hist slot (c-1)&1)
            named_bar(1 + sb, 64);      // rec finished chunk c; hist c complete
        }
        flushc(nchunk - 1);
    } else {
        // ===================== RECURRENCE (warp-synchronous) =====================
        // alpha-scaled W_hh rows 2q, 2q+1 as (k,k+1) pairs
        ull_t wA[32], wB[32];
        {
            const ulonglong2* ra = reinterpret_cast<const ulonglong2*>(W_hh + (2 * q) * H);
            const ulonglong2* rb = reinterpret_cast<const ulonglong2*>(W_hh + (2 * q + 1) * H);
#pragma unroll
            for (int m = 0; m < 16; m++) {
                ulonglong2 va = ra[m], vb = rb[m];
                wA[2 * m] = mul2(va.x, alpha2); wA[2 * m + 1] = mul2(va.y, alpha2);
                wB[2 * m] = mul2(vb.x, alpha2); wB[2 * m + 1] = mul2(vb.y, alpha2);
            }
        }

        float hA = 0.0f, hB = 0.0f;
        hist[sb * 2048 + 63 * 32 + q] = 0ull;   // h_{-1} = 0 (slot 63)
        __syncwarp();
        named_bar(1 + sb, 64);                  // wait xp chunk 0

        for (int c = 0; c < nchunk; c++) {
            const int xr   = c & 1;
            const int tend = min(CH, T - c * CH);
            const ull_t* xps = &xpb[xr * 2048 + sb * 1024];
            const int base = c * CH;

#define STEP(tt)                                                                    \
    {                                                                               \
        const int t = base + (tt);                                                  \
        float xpA, xpB;                                                             \
        unpack2(xpA, xpB, xps[(tt) * 32 + q]);                                      \
        ull_t aA0 = pack2(fmaf(hA, oma, xpA), 0.0f);                                \
        ull_t aB0 = pack2(fmaf(hB, oma, xpB), 0.0f);                                \
        ull_t aA1 = 0ull, aA2 = 0ull, aA3 = 0ull;                                   \
        ull_t aB1 = 0ull, aB2 = 0ull, aB3 = 0ull;                                   \
        const ulonglong2* hp = reinterpret_cast<const ulonglong2*>(                 \
            &hist[sb * 2048 + ((t + 63) & 63) * 32]);                               \
        _Pragma("unroll")                                                           \
        for (int m = 0; m < 16; m++) {                                              \
            ulonglong2 hv = hp[m];                                                  \
            ffma2((m & 1) ? aA1 : aA0, wA[2 * m],     hv.x);                        \
            ffma2((m & 1) ? aA3 : aA2, wA[2 * m + 1], hv.y);                        \
            ffma2((m & 1) ? aB1 : aB0, wB[2 * m],     hv.x);                        \
            ffma2((m & 1) ? aB3 : aB2, wB[2 * m + 1], hv.y);                        \
        }                                                                           \
        float pA = hsum2(add2(add2(aA0, aA1), add2(aA2, aA3)));                     \
        float pB = hsum2(add2(add2(aB0, aB1), add2(aB2, aB3)));                     \
        hA = fmaxf(pA, 0.0f);                                                       \
        hB = fmaxf(pB, 0.0f);                                                       \
        hist[sb * 2048 + (t & 63) * 32 + q] = pack2(hA, hB);                        \
        __syncwarp();                                                               \
    }

            if (tend == CH) {
#pragma unroll 2
                for (int tt = 0; tt < CH; tt++) STEP(tt)
            } else {
                for (int tt = 0; tt < tend; tt++) STEP(tt)
            }
#undef STEP

            named_bar(1 + sb, 64);   // chunk done: flusher may read hist chunk c
        }

        // h_last appended after outputs
        if (active)
            *(ull_t*)(out + (size_t)B * T * H + (size_t)b * H + 2 * q) = pack2(hA, hB);
    }
}

extern "C" void kernel_launch(void* const* d_in, const int* in_sizes, int n_in,
                              void* d_out, int out_size)
{
    const float* x    = (const float*)d_in[0];
    // d_in[1] = seq_lengths: forward-dead (mask only gates gradients)
    const float* W_in = (const float*)d_in[2];
    const float* b_in = (const float*)d_in[3];
    const float* W_hh = (const float*)d_in[4];
    const float* b_hh = (const float*)d_in[5];
    float* out = (float*)d_out;

    const int B = in_sizes[1];
    const int H = in_sizes[5];
    const int D = in_sizes[2] / H;
    const long long T = (long long)in_sizes[0] / ((long long)B * D);

    cudaFuncSetAttribute(ctrnn_ws4_kernel,
                         cudaFuncAttributeMaxDynamicSharedMemorySize, SMEM_TOTAL);

    const int grid = (B + 1) / 2;
    ctrnn_ws4_kernel<<<grid, 128, SMEM_TOTAL>>>(x, W_in, b_in, W_hh, b_hh,
                                                out, B, (int)T);
}